// round 1
// baseline (speedup 1.0000x reference)
#include <cuda_runtime.h>
#include <cuda_bf16.h>
#include <math.h>

// Problem constants
#define B_   2
#define T_   4
#define HH   256
#define WW   256
#define SP_  64
#define NH   7
#define NN   49      // NH*NH
#define CE   512
#define DD   128
#define TEMP_ 0.07f

// ---------------- scratch (device globals; no allocation allowed) ----------------
__device__ float g_ws [B_*T_*NN*SP_];     // (b,t,n,s)
__device__ float g_q  [B_*T_*NN*DD];      // raw projected q, (b,t,n,d)
__device__ float g_qsp[B_*T_*SP_*DD];     // (b,t,s,d)
__device__ float g_A12[B_*3*SP_*SP_];     // (b,t,n,m)
__device__ float g_A21[B_*3*SP_*SP_];     // (b,t,m,n)
__device__ float g_P  [B_*SP_*SP_];
__device__ float g_Mid[B_*SP_*SP_];
__device__ float g_S  [B_*SP_*SP_];
__device__ float g_U  [B_*SP_*SP_];

// ---------------- 1. window sums (ws) ----------------
// block = one (b*t, window). Weight 1/cov(y)/cov(x) where cov == #windows containing pixel.
__global__ void ws_kernel(const int* __restrict__ sp_mask) {
    int w  = blockIdx.x;           // 0..48
    int bt = blockIdx.y;           // 0..7
    int wy = w / NH, wx = w % NH;
    int y0 = wy * 32, x0 = wx * 32;
    __shared__ float hist[SP_];
    int tid = threadIdx.x;         // 256 threads
    if (tid < SP_) hist[tid] = 0.f;
    __syncthreads();
    const int* base = sp_mask + bt * (HH * WW);
    #pragma unroll
    for (int k = 0; k < 16; k++) {
        int p  = tid + k * 256;
        int py = p >> 6, px = p & 63;
        int y = y0 + py, x = x0 + px;
        int s = base[y * WW + x];
        float cy = (y >= 32 && y < 224) ? 0.5f : 1.0f;
        float cx = (x >= 32 && x < 224) ? 0.5f : 1.0f;
        atomicAdd(&hist[s], cy * cx);
    }
    __syncthreads();
    if (tid < SP_) g_ws[(bt * NN + w) * SP_ + tid] = hist[tid];
}

// ---------------- 2. projection q = feats x W_head (raw, un-normalized) ----------------
// grid 49 (n), block 256 = (ch half of K) x (d). 8 accumulators per thread (b x t).
__global__ void proj_kernel(const float* __restrict__ feats,
                            const float* __restrict__ Wh) {
    int n   = blockIdx.x;
    int tid = threadIdx.x;
    int ch  = tid >> 7;      // K half
    int d   = tid & 127;
    __shared__ float sf[2][2][32][4];   // [half][b][cl][t]
    float acc[2][4] = {};
    for (int c0 = 0; c0 < 256; c0 += 32) {
        __syncthreads();
        for (int l = tid; l < 512; l += 256) {
            int t  = l & 3;
            int cl = (l >> 2) & 31;
            int bb = (l >> 7) & 1;
            int hh = l >> 8;
            sf[hh][bb][cl][t] =
                feats[(((size_t)(bb * NN + n)) * CE + hh * 256 + c0 + cl) * T_ + t];
        }
        __syncthreads();
        #pragma unroll
        for (int cl = 0; cl < 32; cl++) {
            float wv = Wh[(ch * 256 + c0 + cl) * DD + d];
            #pragma unroll
            for (int b = 0; b < 2; b++)
                #pragma unroll
                for (int t = 0; t < 4; t++)
                    acc[b][t] = fmaf(sf[ch][b][cl][t], wv, acc[b][t]);
        }
    }
    __shared__ float part[2][8][DD];
    #pragma unroll
    for (int b = 0; b < 2; b++)
        #pragma unroll
        for (int t = 0; t < 4; t++)
            part[ch][b * 4 + t][d] = acc[b][t];
    __syncthreads();
    if (ch == 0) {
        #pragma unroll
        for (int r = 0; r < 8; r++) {
            int b = r >> 2, t = r & 3;
            float v = part[0][r][d] + part[1][r][d];
            g_q[(((b * T_ + t) * NN) + n) * DD + d] = v;
        }
    }
}

// ---------------- 3. q_sp = wts^T x q_normalized, per (b,t) ----------------
__global__ void qsp_kernel() {
    int bt  = blockIdx.x;    // 0..7
    int tid = threadIdx.x;   // 256
    __shared__ float sq[NN][DD];     // raw q tile
    __shared__ float sw[NN][SP_];    // ws tile, later scaled
    __shared__ float sinv[NN];
    __shared__ float sden[SP_];
    const float* qb = g_q  + (size_t)bt * NN * DD;
    const float* wb = g_ws + (size_t)bt * NN * SP_;
    for (int i = tid; i < NN * DD;  i += 256) sq[i / DD][i % DD]   = qb[i];
    for (int i = tid; i < NN * SP_; i += 256) sw[i / SP_][i % SP_] = wb[i];
    __syncthreads();
    // per-row inverse norm (warp per row group)
    int wid = tid >> 5, lane = tid & 31;
    for (int n = wid; n < NN; n += 8) {
        float v0 = sq[n][lane], v1 = sq[n][lane + 32],
              v2 = sq[n][lane + 64], v3 = sq[n][lane + 96];
        float ss = v0 * v0 + v1 * v1 + v2 * v2 + v3 * v3;
        #pragma unroll
        for (int o = 16; o > 0; o >>= 1) ss += __shfl_xor_sync(0xffffffffu, ss, o);
        if (lane == 0) sinv[n] = 1.0f / fmaxf(sqrtf(ss), 1e-12f);
    }
    // denom per s (counts, exact)
    if (tid < SP_) {
        float s = 0.f;
        for (int n = 0; n < NN; n++) s += sw[n][tid];
        sden[tid] = 1.0f / (s + 1e-20f);
    }
    __syncthreads();
    // scale weights: ws * inv_norm(n) * inv_denom(s)
    for (int i = tid; i < NN * SP_; i += 256) {
        int n = i / SP_, s = i % SP_;
        sw[n][s] *= sinv[n] * sden[s];
    }
    __syncthreads();
    // out[s][d] = sum_n sw[n][s] * sq[n][d]
    int s  = tid >> 2;
    int dg = tid & 3;
    float acc[32];
    #pragma unroll
    for (int j = 0; j < 32; j++) acc[j] = 0.f;
    for (int n = 0; n < NN; n++) {
        float w = sw[n][s];
        #pragma unroll
        for (int j = 0; j < 32; j++)
            acc[j] = fmaf(w, sq[n][dg * 32 + j], acc[j]);
    }
    float* ob = g_qsp + ((size_t)bt * SP_ + s) * DD + dg * 32;
    #pragma unroll
    for (int j = 0; j < 32; j++) ob[j] = acc[j];
}

// ---------------- 4. As + zero_softmax -> A12, A21 ----------------
__global__ void as_kernel() {
    int job = blockIdx.x;      // 0..5
    int b = job / 3, t = job % 3;
    const float* X = g_qsp + ((size_t)(b * T_ + t)     * SP_) * DD;
    const float* Y = g_qsp + ((size_t)(b * T_ + t + 1) * SP_) * DD;
    __shared__ float sX[SP_][17], sY[SP_][17];
    __shared__ float sAs[SP_][65];
    __shared__ float rs[SP_], cs[SP_];
    int tid = threadIdx.x;
    int nb = tid >> 4, mb = tid & 15;
    float acc[4][4] = {};
    for (int kc = 0; kc < DD; kc += 16) {
        __syncthreads();
        for (int i = tid; i < 1024; i += 256) {
            int r = i >> 4, kk = i & 15;
            sX[r][kk] = X[r * DD + kc + kk];
            sY[r][kk] = Y[r * DD + kc + kk];
        }
        __syncthreads();
        #pragma unroll
        for (int kk = 0; kk < 16; kk++) {
            float a[4], bb[4];
            #pragma unroll
            for (int i = 0; i < 4; i++) a[i]  = sX[nb * 4 + i][kk];
            #pragma unroll
            for (int i = 0; i < 4; i++) bb[i] = sY[mb * 4 + i][kk];
            #pragma unroll
            for (int i = 0; i < 4; i++)
                #pragma unroll
                for (int j = 0; j < 4; j++)
                    acc[i][j] = fmaf(a[i], bb[j], acc[i][j]);
        }
    }
    __syncthreads();
    #pragma unroll
    for (int i = 0; i < 4; i++)
        #pragma unroll
        for (int j = 0; j < 4; j++) {
            float v = acc[i][j] / TEMP_;
            float e = expf(v) - 1.0f;
            sAs[nb * 4 + i][mb * 4 + j] = e * e;
        }
    __syncthreads();
    if (tid < SP_) {
        float s = 0.f;
        for (int m = 0; m < SP_; m++) s += sAs[tid][m];
        rs[tid] = 1.0f / (s + 1e-5f);
    } else if (tid < 2 * SP_) {
        int c = tid - SP_;
        float s = 0.f;
        for (int n = 0; n < SP_; n++) s += sAs[n][c];
        cs[c] = 1.0f / (s + 1e-5f);
    }
    __syncthreads();
    float* A12 = g_A12 + (size_t)job * SP_ * SP_;
    float* A21 = g_A21 + (size_t)job * SP_ * SP_;
    #pragma unroll
    for (int i = 0; i < 4; i++)
        #pragma unroll
        for (int j = 0; j < 4; j++) {
            int n = nb * 4 + i, m = mb * 4 + j;
            float e = sAs[n][m];
            A12[n * SP_ + m] = e * rs[n];
            A21[m * SP_ + n] = e * cs[m];
        }
}

// ---------------- 5. chain matmuls (tree-reassociated, row-split x4) ----------------
__device__ __forceinline__ void mm16(const float* __restrict__ A,
                                     const float* __restrict__ Bm,
                                     float* __restrict__ C, int r0) {
    __shared__ float sA[16][64];
    __shared__ float sB[64][64];
    int tid = threadIdx.x;
    for (int i = tid; i < 16 * 64; i += 256)
        sA[i >> 6][i & 63] = A[(r0 + (i >> 6)) * 64 + (i & 63)];
    for (int i = tid; i < 64 * 64; i += 256)
        sB[i >> 6][i & 63] = Bm[i];
    __syncthreads();
    int nl = tid >> 4, mg = tid & 15;
    float acc[4] = {0.f, 0.f, 0.f, 0.f};
    #pragma unroll
    for (int k = 0; k < 64; k++) {
        float a = sA[nl][k];
        #pragma unroll
        for (int j = 0; j < 4; j++)
            acc[j] = fmaf(a, sB[k][j * 16 + mg], acc[j]);
    }
    #pragma unroll
    for (int j = 0; j < 4; j++)
        C[(r0 + nl) * 64 + j * 16 + mg] = acc[j];
}

__global__ void chain_l1() {
    int r0  = blockIdx.x * 16;
    int job = blockIdx.y;           // 0..5
    int b = job / 3, kind = job % 3;
    const float *A, *Bm; float *C;
    if (kind == 0)      { A = g_A12 + (b*3+0)*4096; Bm = g_A12 + (b*3+1)*4096; C = g_P   + b*4096; }
    else if (kind == 1) { A = g_A12 + (b*3+2)*4096; Bm = g_A21 + (b*3+2)*4096; C = g_Mid + b*4096; }
    else                { A = g_A21 + (b*3+1)*4096; Bm = g_A21 + (b*3+0)*4096; C = g_S   + b*4096; }
    mm16(A, Bm, C, r0);
}

__global__ void chain_l2(float* __restrict__ out, int aa_base) {
    int r0  = blockIdx.x * 16;
    int job = blockIdx.y;           // 0..3
    int b = job & 1, kind = job >> 1;
    const float *A, *Bm; float *C;
    if (kind == 0) { A = g_P + b*4096; Bm = g_S   + b*4096; C = out + aa_base + b*4096; } // aa(i=1)
    else           { A = g_P + b*4096; Bm = g_Mid + b*4096; C = g_U + b*4096; }
    mm16(A, Bm, C, r0);
}

__global__ void chain_l3(float* __restrict__ out, int aa_base) {
    int r0 = blockIdx.x * 16;
    int b  = blockIdx.y;            // 0..1
    mm16(g_U + b*4096, g_S + b*4096, out + aa_base + (2 + b)*4096, r0);  // aa(i=2)
}

// ---------------- 6. loss (single block, deterministic) ----------------
__global__ void loss_kernel(float* __restrict__ out, int aa_base, int write_loss) {
    __shared__ float red[256];
    int tid = threadIdx.x;          // 256 = 2 chains x 2 b x 64 s
    int chain = tid >> 7;
    int rem   = tid & 127;
    int b = rem >> 6, s = rem & 63;
    const float* aa = out + aa_base + (chain * 2 + b) * 4096 + s * 64;
    float sum = 0.f;
    for (int m = 0; m < 64; m++) sum += aa[m] + 1e-20f;
    float diag = aa[s] + 1e-20f;
    red[tid] = (logf(sum) - logf(diag)) * (1.0f / 128.0f);
    __syncthreads();
    for (int o = 128; o > 0; o >>= 1) {
        if (tid < o) red[tid] += red[tid + o];
        __syncthreads();
    }
    if (tid == 0 && write_loss) out[0] = red[0];
}

// ---------------- launch ----------------
extern "C" void kernel_launch(void* const* d_in, const int* in_sizes, int n_in,
                              void* d_out, int out_size) {
    const float* feats   = (const float*)d_in[0];
    const float* W_head  = (const float*)d_in[1];
    const int*   sp_mask = (const int*)  d_in[2];
    float* out = (float*)d_out;

    // Output layout: [loss, AAs(2,B,64,64)] if room for the scalar; else AAs only.
    int aa_base    = (out_size > 2 * B_ * SP_ * SP_) ? 1 : 0;
    int write_loss = aa_base;

    ws_kernel  <<<dim3(NN, B_ * T_), 256>>>(sp_mask);
    proj_kernel<<<NN, 256>>>(feats, W_head);
    qsp_kernel <<<B_ * T_, 256>>>();
    as_kernel  <<<B_ * (T_ - 1), 256>>>();
    chain_l1   <<<dim3(4, 6), 256>>>();
    chain_l2   <<<dim3(4, 4), 256>>>(out, aa_base);
    chain_l3   <<<dim3(4, 2), 256>>>(out, aa_base);
    loss_kernel<<<1, 256>>>(out, aa_base, write_loss);
}

// round 2
// speedup vs baseline: 1.9026x; 1.9026x over previous
#include <cuda_runtime.h>
#include <cuda_bf16.h>
#include <math.h>

#define B_   2
#define T_   4
#define HH   256
#define WW   256
#define SP_  64
#define NH   7
#define NN   49
#define CE   512
#define DD   128
#define TEMP_ 0.07f

// ---------------- scratch ----------------
__device__ float g_ws   [B_*T_*NN*SP_];        // (bt,n,s)
__device__ float g_qpart[4][B_*T_*NN*DD];      // K-quarter partials of q
__device__ float g_qsp  [B_*T_*SP_*DD];        // (bt,s,d)
__device__ float g_E    [6*SP_*SP_];           // e^2 per job
__device__ float g_rs   [6*SP_];               // row sums
__device__ float g_csp  [6*8*SP_];             // col partial sums per row-block
__device__ float g_A12  [6*SP_*SP_];
__device__ float g_A21  [6*SP_*SP_];
__device__ float g_P    [B_*SP_*SP_];
__device__ float g_Mid  [B_*SP_*SP_];
__device__ float g_S    [B_*SP_*SP_];
__device__ float g_W2   [B_*SP_*SP_];          // Mid*S

// ---------------- 1. fused: ws histograms (blocks 0..391) + proj K-split (392..587) ----------------
__global__ void fused_in_kernel(const int* __restrict__ sp_mask,
                                const float* __restrict__ feats,
                                const float* __restrict__ Wh) {
    int bx = blockIdx.x;
    int tid = threadIdx.x;
    if (bx < 392) {
        // ---- window-sum histogram ----
        int w  = bx % NN;
        int bt = bx / NN;
        int wy = w / NH, wx = w % NH;
        int y0 = wy * 32, x0 = wx * 32;
        __shared__ float hist[2][SP_];
        if (tid < 2 * SP_) hist[tid >> 6][tid & 63] = 0.f;
        __syncthreads();
        int par = (tid >> 5) & 1;
        const int* base = sp_mask + bt * (HH * WW);
        #pragma unroll
        for (int k = 0; k < 16; k++) {
            int p  = tid + k * 256;
            int py = p >> 6, px = p & 63;
            int y = y0 + py, x = x0 + px;
            int s = __ldg(base + y * WW + x);
            float cy = (y >= 32 && y < 224) ? 0.5f : 1.0f;
            float cx = (x >= 32 && x < 224) ? 0.5f : 1.0f;
            atomicAdd(&hist[par][s], cy * cx);
        }
        __syncthreads();
        if (tid < SP_) g_ws[(bt * NN + w) * SP_ + tid] = hist[0][tid] + hist[1][tid];
    } else {
        // ---- projection, one K-quarter ----
        int pid = bx - 392;
        int n   = pid % NN;
        int kq  = pid / NN;
        __shared__ float sf[2][128][4];      // [b][c_local][t]
        __shared__ float partr[2][8][DD];
        {
            int bb = tid >> 7, row = tid & 127;
            const float4* src = (const float4*)feats + ((size_t)(bb * NN + n) * CE + kq * 128 + row);
            *(float4*)&sf[bb][row][0] = *src;
        }
        __syncthreads();
        int ch = tid >> 7, d = tid & 127;
        float acc[2][4] = {};
        const float* wp = Wh + (size_t)(kq * 128 + ch * 64) * DD + d;
        #pragma unroll 8
        for (int cl = 0; cl < 64; cl++) {
            float wv = wp[(size_t)cl * DD];
            float4 f0 = *(const float4*)&sf[0][ch * 64 + cl][0];
            float4 f1 = *(const float4*)&sf[1][ch * 64 + cl][0];
            acc[0][0] = fmaf(f0.x, wv, acc[0][0]);
            acc[0][1] = fmaf(f0.y, wv, acc[0][1]);
            acc[0][2] = fmaf(f0.z, wv, acc[0][2]);
            acc[0][3] = fmaf(f0.w, wv, acc[0][3]);
            acc[1][0] = fmaf(f1.x, wv, acc[1][0]);
            acc[1][1] = fmaf(f1.y, wv, acc[1][1]);
            acc[1][2] = fmaf(f1.z, wv, acc[1][2]);
            acc[1][3] = fmaf(f1.w, wv, acc[1][3]);
        }
        #pragma unroll
        for (int b = 0; b < 2; b++)
            #pragma unroll
            for (int t = 0; t < 4; t++)
                partr[ch][b * 4 + t][d] = acc[b][t];
        __syncthreads();
        if (ch == 0) {
            #pragma unroll
            for (int r = 0; r < 8; r++)
                g_qpart[kq][((size_t)r * NN + n) * DD + d] = partr[0][r][d] + partr[1][r][d];
        }
    }
}

// ---------------- 2. qsp: reduce partials, normalize, build weights, small GEMM ----------------
__global__ void qsp_kernel() {
    int bx  = blockIdx.x;       // 32 blocks
    int bt  = bx >> 2;
    int dq  = bx & 3;
    int tid = threadIdx.x;
    __shared__ float sq[NN][DD];     // 25 KB
    __shared__ float sw[NN][SP_];    // 12.25 KB
    __shared__ float sinv[NN];
    __shared__ float sden[SP_];
    // reduce 4 K-partials
    for (int i = tid; i < NN * DD; i += 256) {
        size_t off = (size_t)bt * NN * DD + i;
        sq[i >> 7][i & 127] = g_qpart[0][off] + g_qpart[1][off] + g_qpart[2][off] + g_qpart[3][off];
    }
    for (int i = tid; i < NN * SP_; i += 256)
        sw[i >> 6][i & 63] = g_ws[(size_t)bt * NN * SP_ + i];
    __syncthreads();
    int wid = tid >> 5, lane = tid & 31;
    for (int n = wid; n < NN; n += 8) {
        float v0 = sq[n][lane], v1 = sq[n][lane + 32],
              v2 = sq[n][lane + 64], v3 = sq[n][lane + 96];
        float ss = v0 * v0 + v1 * v1 + v2 * v2 + v3 * v3;
        #pragma unroll
        for (int o = 16; o > 0; o >>= 1) ss += __shfl_xor_sync(0xffffffffu, ss, o);
        if (lane == 0) sinv[n] = 1.0f / fmaxf(sqrtf(ss), 1e-12f);
    }
    if (tid < SP_) {
        float s = 0.f;
        for (int n = 0; n < NN; n++) s += sw[n][tid];
        sden[tid] = 1.0f / (s + 1e-20f);
    }
    __syncthreads();
    for (int i = tid; i < NN * SP_; i += 256) {
        int n = i >> 6, s = i & 63;
        sw[n][s] *= sinv[n] * sden[s];
    }
    __syncthreads();
    int d  = tid & 31;
    int dd = dq * 32 + d;
    int sg = tid >> 5;          // warp = 8-s group
    float acc[8] = {};
    for (int n = 0; n < NN; n++) {
        float qv = sq[n][dd];
        #pragma unroll
        for (int i = 0; i < 8; i++)
            acc[i] = fmaf(sw[n][sg * 8 + i], qv, acc[i]);
    }
    #pragma unroll
    for (int i = 0; i < 8; i++)
        g_qsp[((size_t)bt * SP_ + sg * 8 + i) * DD + dd] = acc[i];
}

// ---------------- 3. as1: e^2 strips + row sums + column partials ----------------
__global__ void as1_kernel() {
    int bx  = blockIdx.x;        // 48
    int job = bx >> 3;
    int rb  = bx & 7;
    int r0  = rb * 8;
    int b = job / 3, t = job % 3;
    const float* X = g_qsp + (size_t)(b * T_ + t)     * SP_ * DD;
    const float* Y = g_qsp + (size_t)(b * T_ + t + 1) * SP_ * DD;
    __shared__ float sYt[DD][65];   // transposed, padded -> conflict-free
    __shared__ float sXr[8][DD];
    __shared__ float sE[8][65];
    int tid = threadIdx.x;
    for (int i = tid; i < SP_ * DD; i += 256) {
        int m = i >> 7, k = i & 127;
        sYt[k][m] = Y[i];
    }
    for (int i = tid; i < 8 * DD; i += 256) {
        int r = i >> 7, k = i & 127;
        sXr[r][k] = X[(size_t)(r0 + r) * DD + k];
    }
    __syncthreads();
    int m  = tid & 63;
    int lr = (tid >> 6) * 2;
    float a0 = 0.f, a1 = 0.f;
    #pragma unroll 8
    for (int k = 0; k < DD; k++) {
        float yv = sYt[k][m];
        a0 = fmaf(sXr[lr][k],     yv, a0);
        a1 = fmaf(sXr[lr + 1][k], yv, a1);
    }
    float e0 = expf(a0 * (1.0f / TEMP_)) - 1.0f;
    float e1 = expf(a1 * (1.0f / TEMP_)) - 1.0f;
    e0 *= e0; e1 *= e1;
    sE[lr][m] = e0; sE[lr + 1][m] = e1;
    g_E[(size_t)job * 4096 + (r0 + lr) * 64 + m]     = e0;
    g_E[(size_t)job * 4096 + (r0 + lr + 1) * 64 + m] = e1;
    __syncthreads();
    if (tid < 8) {
        float s = 0.f;
        for (int j = 0; j < 64; j++) s += sE[tid][j];
        g_rs[job * 64 + r0 + tid] = s;
    } else if (tid >= 64 && tid < 128) {
        int c = tid - 64;
        float s = 0.f;
        #pragma unroll
        for (int r = 0; r < 8; r++) s += sE[r][c];
        g_csp[(job * 8 + rb) * 64 + c] = s;
    }
}

// ---------------- 4. as2: normalize -> A12, A21 ----------------
__global__ void as2_kernel() {
    int job = blockIdx.x;
    int tid = threadIdx.x;
    __shared__ float rinv[SP_], cinv[SP_];
    if (tid < SP_) {
        rinv[tid] = 1.0f / (g_rs[job * 64 + tid] + 1e-5f);
    } else if (tid < 2 * SP_) {
        int c = tid - SP_;
        float s = 0.f;
        #pragma unroll
        for (int rb = 0; rb < 8; rb++) s += g_csp[(job * 8 + rb) * 64 + c];
        cinv[c] = 1.0f / (s + 1e-5f);
    }
    __syncthreads();
    for (int i = tid; i < 4096; i += 256) {
        int n = i >> 6, m = i & 63;
        float e = g_E[(size_t)job * 4096 + i];
        g_A12[(size_t)job * 4096 + i]           = e * rinv[n];
        g_A21[(size_t)job * 4096 + m * 64 + n]  = e * cinv[m];
    }
}

// ---------------- 5. chain matmuls ----------------
__device__ __forceinline__ void mm16(const float* __restrict__ A,
                                     const float* __restrict__ Bm,
                                     float* __restrict__ C, int r0,
                                     float* acc_out, int* nl_out, int* mg_out) {
    __shared__ float sA[16][64];
    __shared__ float sB[64][64];
    int tid = threadIdx.x;
    for (int i = tid; i < 16 * 64; i += 256)
        sA[i >> 6][i & 63] = A[(r0 + (i >> 6)) * 64 + (i & 63)];
    for (int i = tid; i < 64 * 64; i += 256)
        sB[i >> 6][i & 63] = Bm[i];
    __syncthreads();
    int nl = tid >> 4, mg = tid & 15;
    float acc[4] = {0.f, 0.f, 0.f, 0.f};
    #pragma unroll 8
    for (int k = 0; k < 64; k++) {
        float a = sA[nl][k];
        #pragma unroll
        for (int j = 0; j < 4; j++)
            acc[j] = fmaf(a, sB[k][j * 16 + mg], acc[j]);
    }
    #pragma unroll
    for (int j = 0; j < 4; j++) {
        C[(r0 + nl) * 64 + j * 16 + mg] = acc[j];
        acc_out[j] = acc[j];
    }
    *nl_out = nl; *mg_out = mg;
}

__device__ __forceinline__ void loss_part(const float* acc, int nl, int mg, int r0,
                                          float* loss_out) {
    __shared__ float sp[16][17];
    __shared__ float sdg[16];
    __shared__ float sl[16];
    sp[nl][mg] = acc[0] + acc[1] + acc[2] + acc[3];
    int dcol = r0 + nl;                // diag column for this row (row index mod 64)
    int dc = dcol & 63;
    if ((dc & 15) == mg) sdg[nl] = acc[dc >> 4];
    __syncthreads();
    int tid = threadIdx.x;
    if (tid < 16) {
        float rs = 0.f;
        #pragma unroll
        for (int j = 0; j < 16; j++) rs += sp[tid][j];
        sl[tid] = logf(rs + 6.4e-19f) - logf(sdg[tid] + 1e-20f);
    }
    __syncthreads();
    if (tid == 0) {
        float s = 0.f;
        #pragma unroll
        for (int j = 0; j < 16; j++) s += sl[j];
        atomicAdd(loss_out, s * (1.0f / 128.0f));
    }
}

__global__ void chain_l1() {
    int r0  = blockIdx.x * 16;
    int job = blockIdx.y;           // 0..5
    int b = job / 3, kind = job % 3;
    const float *A, *Bm; float *C;
    if (kind == 0)      { A = g_A12 + (b*3+0)*4096; Bm = g_A12 + (b*3+1)*4096; C = g_P   + b*4096; }
    else if (kind == 1) { A = g_A12 + (b*3+2)*4096; Bm = g_A21 + (b*3+2)*4096; C = g_Mid + b*4096; }
    else                { A = g_A21 + (b*3+1)*4096; Bm = g_A21 + (b*3+0)*4096; C = g_S   + b*4096; }
    float acc[4]; int nl, mg;
    mm16(A, Bm, C, r0, acc, &nl, &mg);
}

__global__ void chain_l2(float* __restrict__ out, int aa_base, int write_loss) {
    int r0  = blockIdx.x * 16;
    int job = blockIdx.y;           // 0..3
    int b = job & 1, kind = job >> 1;
    float acc[4]; int nl, mg;
    if (kind == 0) {   // aa1 = P * S  (+ loss)
        float* C = out + aa_base + b * 4096;
        mm16(g_P + b*4096, g_S + b*4096, C, r0, acc, &nl, &mg);
        if (write_loss) loss_part(acc, nl, mg, r0, out);
    } else {           // W2 = Mid * S
        mm16(g_Mid + b*4096, g_S + b*4096, g_W2 + b*4096, r0, acc, &nl, &mg);
    }
}

__global__ void chain_l3(float* __restrict__ out, int aa_base, int write_loss) {
    int r0 = blockIdx.x * 16;
    int b  = blockIdx.y;            // 0..1
    float acc[4]; int nl, mg;
    float* C = out + aa_base + (2 + b) * 4096;   // aa2 = P * (Mid*S)
    mm16(g_P + b*4096, g_W2 + b*4096, C, r0, acc, &nl, &mg);
    if (write_loss) loss_part(acc, nl, mg, r0, out);
}

// ---------------- launch ----------------
extern "C" void kernel_launch(void* const* d_in, const int* in_sizes, int n_in,
                              void* d_out, int out_size) {
    const float* feats   = (const float*)d_in[0];
    const float* W_head  = (const float*)d_in[1];
    const int*   sp_mask = (const int*)  d_in[2];
    float* out = (float*)d_out;

    int aa_base    = (out_size > 2 * B_ * SP_ * SP_) ? 1 : 0;
    int write_loss = aa_base;

    if (write_loss) cudaMemsetAsync(out, 0, sizeof(float), 0);
    fused_in_kernel<<<588, 256>>>(sp_mask, feats, W_head);
    qsp_kernel     <<<32, 256>>>();
    as1_kernel     <<<48, 256>>>();
    as2_kernel     <<<6, 256>>>();
    chain_l1       <<<dim3(4, 6), 256>>>();
    chain_l2       <<<dim3(4, 4), 256>>>(out, aa_base, write_loss);
    chain_l3       <<<dim3(4, 2), 256>>>(out, aa_base, write_loss);
}

// round 4
// speedup vs baseline: 2.5860x; 1.3592x over previous
#include <cuda_runtime.h>
#include <cuda_bf16.h>
#include <math.h>

#define B_   2
#define T_   4
#define HH   256
#define WW   256
#define SP_  64
#define NH   7
#define NN   49
#define CE   512
#define DD   128
#define TEMP_ 0.07f

// ---------------- scratch ----------------
__device__ float g_ws   [B_*T_*NN*SP_];
__device__ float g_qpart[4][B_*T_*NN*DD];
__device__ float g_qsp  [B_*T_*SP_*DD];
__device__ float g_E    [6*SP_*SP_];
__device__ float g_rs   [6*SP_];
__device__ float g_csp  [6*8*SP_];
__device__ float g_A12  [6*SP_*SP_];
__device__ float g_A21  [6*SP_*SP_];

// ---------------- 1. fused: ws histograms + proj K-split ----------------
__global__ void fused_in_kernel(const int* __restrict__ sp_mask,
                                const float* __restrict__ feats,
                                const float* __restrict__ Wh,
                                float* __restrict__ out, int write_loss) {
    int bx = blockIdx.x;
    int tid = threadIdx.x;
    if (bx == 0 && tid == 0 && write_loss) out[0] = 0.f;
    if (bx < 392) {
        int w  = bx % NN;
        int bt = bx / NN;
        int wy = w / NH, wx = w % NH;
        int y0 = wy * 32, x0 = wx * 32;
        __shared__ float hist[2][SP_];
        if (tid < 2 * SP_) hist[tid >> 6][tid & 63] = 0.f;
        __syncthreads();
        int par = (tid >> 5) & 1;
        const int* base = sp_mask + bt * (HH * WW);
        #pragma unroll
        for (int k = 0; k < 16; k++) {
            int p  = tid + k * 256;
            int py = p >> 6, px = p & 63;
            int y = y0 + py, x = x0 + px;
            int s = __ldg(base + y * WW + x);
            float cy = (y >= 32 && y < 224) ? 0.5f : 1.0f;
            float cx = (x >= 32 && x < 224) ? 0.5f : 1.0f;
            atomicAdd(&hist[par][s], cy * cx);
        }
        __syncthreads();
        if (tid < SP_) g_ws[(bt * NN + w) * SP_ + tid] = hist[0][tid] + hist[1][tid];
    } else {
        int pid = bx - 392;
        int n   = pid % NN;
        int kq  = pid / NN;
        __shared__ float sf[2][128][4];
        __shared__ float partr[2][8][DD];
        {
            int bb = tid >> 7, row = tid & 127;
            const float4* src = (const float4*)feats + ((size_t)(bb * NN + n) * CE + kq * 128 + row);
            *(float4*)&sf[bb][row][0] = *src;
        }
        __syncthreads();
        int ch = tid >> 7, d = tid & 127;
        float acc[2][4] = {};
        const float* wp = Wh + (size_t)(kq * 128 + ch * 64) * DD + d;
        #pragma unroll 8
        for (int cl = 0; cl < 64; cl++) {
            float wv = wp[(size_t)cl * DD];
            float4 f0 = *(const float4*)&sf[0][ch * 64 + cl][0];
            float4 f1 = *(const float4*)&sf[1][ch * 64 + cl][0];
            acc[0][0] = fmaf(f0.x, wv, acc[0][0]);
            acc[0][1] = fmaf(f0.y, wv, acc[0][1]);
            acc[0][2] = fmaf(f0.z, wv, acc[0][2]);
            acc[0][3] = fmaf(f0.w, wv, acc[0][3]);
            acc[1][0] = fmaf(f1.x, wv, acc[1][0]);
            acc[1][1] = fmaf(f1.y, wv, acc[1][1]);
            acc[1][2] = fmaf(f1.z, wv, acc[1][2]);
            acc[1][3] = fmaf(f1.w, wv, acc[1][3]);
        }
        #pragma unroll
        for (int b = 0; b < 2; b++)
            #pragma unroll
            for (int t = 0; t < 4; t++)
                partr[ch][b * 4 + t][d] = acc[b][t];
        __syncthreads();
        if (ch == 0) {
            #pragma unroll
            for (int r = 0; r < 8; r++)
                g_qpart[kq][((size_t)r * NN + n) * DD + d] = partr[0][r][d] + partr[1][r][d];
        }
    }
}

// ---------------- 2. qsp ----------------
__global__ void qsp_kernel() {
    int bx  = blockIdx.x;
    int bt  = bx >> 2;
    int dq  = bx & 3;
    int tid = threadIdx.x;
    __shared__ float sq[NN][DD];
    __shared__ float sw[NN][SP_];
    __shared__ float sinv[NN];
    __shared__ float sden[SP_];
    for (int i = tid; i < NN * DD; i += 256) {
        size_t off = (size_t)bt * NN * DD + i;
        sq[i >> 7][i & 127] = g_qpart[0][off] + g_qpart[1][off] + g_qpart[2][off] + g_qpart[3][off];
    }
    for (int i = tid; i < NN * SP_; i += 256)
        sw[i >> 6][i & 63] = g_ws[(size_t)bt * NN * SP_ + i];
    __syncthreads();
    int wid = tid >> 5, lane = tid & 31;
    for (int n = wid; n < NN; n += 8) {
        float v0 = sq[n][lane], v1 = sq[n][lane + 32],
              v2 = sq[n][lane + 64], v3 = sq[n][lane + 96];
        float ss = v0 * v0 + v1 * v1 + v2 * v2 + v3 * v3;
        #pragma unroll
        for (int o = 16; o > 0; o >>= 1) ss += __shfl_xor_sync(0xffffffffu, ss, o);
        if (lane == 0) sinv[n] = 1.0f / fmaxf(sqrtf(ss), 1e-12f);
    }
    if (tid < SP_) {
        float s = 0.f;
        for (int n = 0; n < NN; n++) s += sw[n][tid];
        sden[tid] = 1.0f / (s + 1e-20f);
    }
    __syncthreads();
    for (int i = tid; i < NN * SP_; i += 256) {
        int n = i >> 6, s = i & 63;
        sw[n][s] *= sinv[n] * sden[s];
    }
    __syncthreads();
    int d  = tid & 31;
    int dd = dq * 32 + d;
    int sg = tid >> 5;
    float acc[8] = {};
    for (int n = 0; n < NN; n++) {
        float qv = sq[n][dd];
        #pragma unroll
        for (int i = 0; i < 8; i++)
            acc[i] = fmaf(sw[n][sg * 8 + i], qv, acc[i]);
    }
    #pragma unroll
    for (int i = 0; i < 8; i++)
        g_qsp[((size_t)bt * SP_ + sg * 8 + i) * DD + dd] = acc[i];
}

// ---------------- 3. as1 ----------------
__global__ void as1_kernel() {
    int bx  = blockIdx.x;        // 48
    int job = bx >> 3;
    int rb  = bx & 7;
    int r0  = rb * 8;
    int b = job / 3, t = job % 3;
    const float* X = g_qsp + (size_t)(b * T_ + t)     * SP_ * DD;
    const float* Y = g_qsp + (size_t)(b * T_ + t + 1) * SP_ * DD;
    __shared__ float sYt[DD][65];
    __shared__ float sXr[8][DD];
    __shared__ float sE[8][65];
    int tid = threadIdx.x;
    for (int i = tid; i < SP_ * DD; i += 256) {
        int m = i >> 7, k = i & 127;
        sYt[k][m] = Y[i];
    }
    for (int i = tid; i < 8 * DD; i += 256) {
        int r = i >> 7, k = i & 127;
        sXr[r][k] = X[(size_t)(r0 + r) * DD + k];
    }
    __syncthreads();
    int m  = tid & 63;
    int lr = (tid >> 6) * 2;
    float a0 = 0.f, a1 = 0.f;
    #pragma unroll 8
    for (int k = 0; k < DD; k++) {
        float yv = sYt[k][m];
        a0 = fmaf(sXr[lr][k],     yv, a0);
        a1 = fmaf(sXr[lr + 1][k], yv, a1);
    }
    float e0 = expf(a0 * (1.0f / TEMP_)) - 1.0f;
    float e1 = expf(a1 * (1.0f / TEMP_)) - 1.0f;
    e0 *= e0; e1 *= e1;
    sE[lr][m] = e0; sE[lr + 1][m] = e1;
    g_E[(size_t)job * 4096 + (r0 + lr) * 64 + m]     = e0;
    g_E[(size_t)job * 4096 + (r0 + lr + 1) * 64 + m] = e1;
    __syncthreads();
    if (tid < 8) {
        float s = 0.f;
        for (int j = 0; j < 64; j++) s += sE[tid][j];
        g_rs[job * 64 + r0 + tid] = s;
    } else if (tid >= 64 && tid < 128) {
        int c = tid - 64;
        float s = 0.f;
        #pragma unroll
        for (int r = 0; r < 8; r++) s += sE[r][c];
        g_csp[(job * 8 + rb) * 64 + c] = s;
    }
}

// ---------------- 4. as2 (proven R2 math, 48-block row-strip split) ----------------
__global__ void as2_kernel() {
    int job = blockIdx.x >> 3;    // 0..5
    int rb  = blockIdx.x & 7;
    int r0  = rb * 8;
    int tid = threadIdx.x;
    __shared__ float rinv[8], cinv[SP_];
    if (tid < 8) {
        rinv[tid] = 1.0f / (g_rs[job * 64 + r0 + tid] + 1e-5f);
    } else if (tid >= 64 && tid < 128) {
        int c = tid - 64;
        float s = 0.f;
        #pragma unroll
        for (int rr = 0; rr < 8; rr++) s += g_csp[(job * 8 + rr) * 64 + c];
        cinv[c] = 1.0f / (s + 1e-5f);
    }
    __syncthreads();
    for (int i = tid; i < 512; i += 256) {
        int r = i >> 6, m = i & 63;
        int n = r0 + r;
        float e = g_E[(size_t)job * 4096 + n * 64 + m];
        g_A12[(size_t)job * 4096 + n * 64 + m] = e * rinv[r];
        g_A21[(size_t)job * 4096 + m * 64 + n] = e * cinv[m];
    }
}

// ---------------- 5. chain: load normalized mats, product chain + aa + loss ----------------
#define MSTRIDE 65
#define BSTRIDE 68
#define SMEM_CHAIN ((5*64*MSTRIDE + 3*8*BSTRIDE + 16 + 16) * 4)

__device__ __forceinline__ void mm8(const float* __restrict__ In,
                                    const float* __restrict__ Bm,
                                    float* __restrict__ Out) {
    int tid = threadIdx.x;
    int rg = tid >> 6, m = tid & 63;
    const float* a0p = In + (2 * rg)     * BSTRIDE;
    const float* a1p = In + (2 * rg + 1) * BSTRIDE;
    float acc0 = 0.f, acc1 = 0.f;
    #pragma unroll
    for (int k4 = 0; k4 < 16; k4++) {
        float4 a0 = *(const float4*)(a0p + k4 * 4);
        float4 a1 = *(const float4*)(a1p + k4 * 4);
        float b0 = Bm[(k4 * 4 + 0) * MSTRIDE + m];
        float b1 = Bm[(k4 * 4 + 1) * MSTRIDE + m];
        float b2 = Bm[(k4 * 4 + 2) * MSTRIDE + m];
        float b3 = Bm[(k4 * 4 + 3) * MSTRIDE + m];
        acc0 = fmaf(a0.x, b0, acc0); acc0 = fmaf(a0.y, b1, acc0);
        acc0 = fmaf(a0.z, b2, acc0); acc0 = fmaf(a0.w, b3, acc0);
        acc1 = fmaf(a1.x, b0, acc1); acc1 = fmaf(a1.y, b1, acc1);
        acc1 = fmaf(a1.z, b2, acc1); acc1 = fmaf(a1.w, b3, acc1);
    }
    Out[(2 * rg) * BSTRIDE + m] = acc0;
    Out[(2 * rg + 1) * BSTRIDE + m] = acc1;
    __syncthreads();
}

__device__ __forceinline__ void emit_aa(const float* __restrict__ buf,
                                        float* __restrict__ out, int aa_base,
                                        int chain, int b, int r0,
                                        float* __restrict__ slloss, int write_loss) {
    int tid = threadIdx.x;
    float* dst = out + aa_base + (size_t)(chain * B_ + b) * 4096;
    for (int i = tid; i < 512; i += 256) {
        int r = i >> 6, m = i & 63;
        dst[(r0 + r) * 64 + m] = buf[r * BSTRIDE + m];
    }
    if (write_loss && tid < 8) {
        float s = 0.f;
        #pragma unroll 8
        for (int j = 0; j < 64; j++) s += buf[tid * BSTRIDE + j];
        float diag = buf[tid * BSTRIDE + (r0 + tid)] + 1e-20f;
        slloss[chain * 8 + tid] = logf(s + 6.4e-19f) - logf(diag);
    }
    __syncthreads();
}

__global__ void chain_kernel(float* __restrict__ out, int aa_base, int write_loss) {
    extern __shared__ float sm[];
    float* A12_1 = sm;
    float* A12_2 = sm + 1 * 64 * MSTRIDE;
    float* A21_2 = sm + 2 * 64 * MSTRIDE;
    float* A21_1 = sm + 3 * 64 * MSTRIDE;
    float* A21_0 = sm + 4 * 64 * MSTRIDE;
    float* buf0  = sm + 5 * 64 * MSTRIDE;
    float* buf1  = buf0 + 8 * BSTRIDE;
    float* bufP  = buf1 + 8 * BSTRIDE;
    float* slloss = bufP + 8 * BSTRIDE;    // [16]
    int b  = blockIdx.y;
    int r0 = blockIdx.x * 8;
    int tid = threadIdx.x;
    int j0 = b * 3, j1 = j0 + 1, j2 = j0 + 2;

    // straight loads of pre-normalized matrices (coalesced)
    const float* gA12_1 = g_A12 + (size_t)j1 * 4096;
    const float* gA12_2 = g_A12 + (size_t)j2 * 4096;
    const float* gA21_2 = g_A21 + (size_t)j2 * 4096;
    const float* gA21_1 = g_A21 + (size_t)j1 * 4096;
    const float* gA21_0 = g_A21 + (size_t)j0 * 4096;
    for (int i = tid; i < 4096; i += 256) {
        int n = i >> 6, m = i & 63;
        int idx = n * MSTRIDE + m;
        A12_1[idx] = gA12_1[i];
        A12_2[idx] = gA12_2[i];
        A21_2[idx] = gA21_2[i];
        A21_1[idx] = gA21_1[i];
        A21_0[idx] = gA21_0[i];
    }
    for (int i = tid; i < 512; i += 256) {
        int r = i >> 6, m = i & 63;
        buf0[r * BSTRIDE + m] = g_A12[(size_t)j0 * 4096 + (r0 + r) * 64 + m];
    }
    __syncthreads();

    mm8(buf0, A12_1, bufP);            // P = A12_0slice @ A12_1
    mm8(bufP, A21_1, buf0);            // P @ A21_1
    mm8(buf0, A21_0, buf1);            // aa1 slice
    emit_aa(buf1, out, aa_base, 0, b, r0, slloss, write_loss);
    mm8(bufP, A12_2, buf0);            // P @ A12_2
    mm8(buf0, A21_2, buf1);
    mm8(buf1, A21_1, buf0);
    mm8(buf0, A21_0, buf1);            // aa2 slice
    emit_aa(buf1, out, aa_base, 1, b, r0, slloss, write_loss);

    if (write_loss && tid == 0) {
        float s = 0.f;
        #pragma unroll
        for (int j = 0; j < 16; j++) s += slloss[j];
        atomicAdd(out, s * (1.0f / 128.0f));
    }
}

// ---------------- launch ----------------
extern "C" void kernel_launch(void* const* d_in, const int* in_sizes, int n_in,
                              void* d_out, int out_size) {
    const float* feats   = (const float*)d_in[0];
    const float* W_head  = (const float*)d_in[1];
    const int*   sp_mask = (const int*)  d_in[2];
    float* out = (float*)d_out;

    int aa_base    = (out_size > 2 * B_ * SP_ * SP_) ? 1 : 0;
    int write_loss = aa_base;

    cudaFuncSetAttribute(chain_kernel, cudaFuncAttributeMaxDynamicSharedMemorySize, SMEM_CHAIN);

    fused_in_kernel<<<588, 256>>>(sp_mask, feats, W_head, out, write_loss);
    qsp_kernel     <<<32, 256>>>();
    as1_kernel     <<<48, 256>>>();
    as2_kernel     <<<48, 256>>>();
    chain_kernel   <<<dim3(8, 2), 256, SMEM_CHAIN>>>(out, aa_base, write_loss);
}

// round 5
// speedup vs baseline: 2.6012x; 1.0059x over previous
#include <cuda_runtime.h>
#include <cuda_bf16.h>
#include <math.h>

#define B_   2
#define T_   4
#define HH   256
#define WW   256
#define SP_  64
#define NH   7
#define NN   49
#define CE   512
#define DD   128
#define TEMP_ 0.07f

// ---------------- scratch ----------------
__device__ float g_ws   [B_*T_*NN*SP_];
__device__ float g_qpart[4][B_*T_*NN*DD];
__device__ float g_qsp  [B_*T_*SP_*DD];
__device__ float g_E    [6*SP_*SP_];
__device__ float g_rs   [6*SP_];
__device__ float g_csp  [6*8*SP_];
__device__ unsigned g_barcnt[2];   // monotonic, replay-safe

// ---------------- 1. fused: ws histograms + proj K-split ----------------
__global__ void fused_in_kernel(const int* __restrict__ sp_mask,
                                const float* __restrict__ feats,
                                const float* __restrict__ Wh,
                                float* __restrict__ out, int write_loss) {
    int bx = blockIdx.x;
    int tid = threadIdx.x;
    if (bx == 0 && tid == 0 && write_loss) out[0] = 0.f;
    if (bx < 392) {
        int w  = bx % NN;
        int bt = bx / NN;
        int wy = w / NH, wx = w % NH;
        int y0 = wy * 32, x0 = wx * 32;
        __shared__ float hist[2][SP_];
        if (tid < 2 * SP_) hist[tid >> 6][tid & 63] = 0.f;
        __syncthreads();
        int par = (tid >> 5) & 1;
        const int* base = sp_mask + bt * (HH * WW);
        #pragma unroll
        for (int k = 0; k < 16; k++) {
            int p  = tid + k * 256;
            int py = p >> 6, px = p & 63;
            int y = y0 + py, x = x0 + px;
            int s = __ldg(base + y * WW + x);
            float cy = (y >= 32 && y < 224) ? 0.5f : 1.0f;
            float cx = (x >= 32 && x < 224) ? 0.5f : 1.0f;
            atomicAdd(&hist[par][s], cy * cx);
        }
        __syncthreads();
        if (tid < SP_) g_ws[(bt * NN + w) * SP_ + tid] = hist[0][tid] + hist[1][tid];
    } else {
        int pid = bx - 392;
        int n   = pid % NN;
        int kq  = pid / NN;
        __shared__ float sf[2][128][4];
        __shared__ float partr[2][8][DD];
        {
            int bb = tid >> 7, row = tid & 127;
            const float4* src = (const float4*)feats + ((size_t)(bb * NN + n) * CE + kq * 128 + row);
            *(float4*)&sf[bb][row][0] = *src;
        }
        __syncthreads();
        int ch = tid >> 7, d = tid & 127;
        float acc[2][4] = {};
        const float* wp = Wh + (size_t)(kq * 128 + ch * 64) * DD + d;
        #pragma unroll 8
        for (int cl = 0; cl < 64; cl++) {
            float wv = wp[(size_t)cl * DD];
            float4 f0 = *(const float4*)&sf[0][ch * 64 + cl][0];
            float4 f1 = *(const float4*)&sf[1][ch * 64 + cl][0];
            acc[0][0] = fmaf(f0.x, wv, acc[0][0]);
            acc[0][1] = fmaf(f0.y, wv, acc[0][1]);
            acc[0][2] = fmaf(f0.z, wv, acc[0][2]);
            acc[0][3] = fmaf(f0.w, wv, acc[0][3]);
            acc[1][0] = fmaf(f1.x, wv, acc[1][0]);
            acc[1][1] = fmaf(f1.y, wv, acc[1][1]);
            acc[1][2] = fmaf(f1.z, wv, acc[1][2]);
            acc[1][3] = fmaf(f1.w, wv, acc[1][3]);
        }
        #pragma unroll
        for (int b = 0; b < 2; b++)
            #pragma unroll
            for (int t = 0; t < 4; t++)
                partr[ch][b * 4 + t][d] = acc[b][t];
        __syncthreads();
        if (ch == 0) {
            #pragma unroll
            for (int r = 0; r < 8; r++)
                g_qpart[kq][((size_t)r * NN + n) * DD + d] = partr[0][r][d] + partr[1][r][d];
        }
    }
}

// ---------------- grid barrier (monotonic counter; all 48 blocks co-resident) ----------------
#define NBLK 48
__device__ __forceinline__ void gridbar(int slot) {
    __syncthreads();
    __threadfence();
    if (threadIdx.x == 0) {
        unsigned my = atomicAdd(&g_barcnt[slot], 1u) + 1u;
        unsigned target = ((my + NBLK - 1u) / NBLK) * NBLK;
        while (*(volatile unsigned*)&g_barcnt[slot] < target) { }
    }
    __syncthreads();
    __threadfence();
}

// ---------------- 2. mega tail: qsp -> as1 -> chain (+loss) ----------------
#define MSTRIDE 65
#define BSTRIDE 68
// phase3 is the biggest: 5*64*65 + 3*8*68 + 384 + 16 = 23232 floats (rounded up)
#define SMEM_MEGA (23232 * 4)

__device__ __forceinline__ void mm8(const float* __restrict__ In,
                                    const float* __restrict__ Bm,
                                    float* __restrict__ Out) {
    int tid = threadIdx.x;
    int rg = tid >> 6, m = tid & 63;
    const float* a0p = In + (2 * rg)     * BSTRIDE;
    const float* a1p = In + (2 * rg + 1) * BSTRIDE;
    float acc0 = 0.f, acc1 = 0.f;
    #pragma unroll
    for (int k4 = 0; k4 < 16; k4++) {
        float4 a0 = *(const float4*)(a0p + k4 * 4);
        float4 a1 = *(const float4*)(a1p + k4 * 4);
        float b0 = Bm[(k4 * 4 + 0) * MSTRIDE + m];
        float b1 = Bm[(k4 * 4 + 1) * MSTRIDE + m];
        float b2 = Bm[(k4 * 4 + 2) * MSTRIDE + m];
        float b3 = Bm[(k4 * 4 + 3) * MSTRIDE + m];
        acc0 = fmaf(a0.x, b0, acc0); acc0 = fmaf(a0.y, b1, acc0);
        acc0 = fmaf(a0.z, b2, acc0); acc0 = fmaf(a0.w, b3, acc0);
        acc1 = fmaf(a1.x, b0, acc1); acc1 = fmaf(a1.y, b1, acc1);
        acc1 = fmaf(a1.z, b2, acc1); acc1 = fmaf(a1.w, b3, acc1);
    }
    Out[(2 * rg) * BSTRIDE + m] = acc0;
    Out[(2 * rg + 1) * BSTRIDE + m] = acc1;
    __syncthreads();
}

__device__ __forceinline__ void emit_aa(const float* __restrict__ buf,
                                        float* __restrict__ out, int aa_base,
                                        int chain, int b, int r0,
                                        float* __restrict__ slloss, int write_loss) {
    int tid = threadIdx.x;
    float* dst = out + aa_base + (size_t)(chain * B_ + b) * 4096;
    for (int i = tid; i < 512; i += 256) {
        int r = i >> 6, m = i & 63;
        dst[(r0 + r) * 64 + m] = buf[r * BSTRIDE + m];
    }
    if (write_loss && tid < 8) {
        float s = 0.f;
        #pragma unroll 8
        for (int j = 0; j < 64; j++) s += buf[tid * BSTRIDE + j];
        float diag = buf[tid * BSTRIDE + (r0 + tid)] + 1e-20f;
        slloss[chain * 8 + tid] = logf(s + 6.4e-19f) - logf(diag);
    }
    __syncthreads();
}

__global__ void mega_kernel(float* __restrict__ out, int aa_base, int write_loss) {
    extern __shared__ float sm[];
    int bx  = blockIdx.x;     // 0..47
    int tid = threadIdx.x;

    // ======== phase 1: qsp (blocks 0..31) ========
    if (bx < 32) {
        int bt = bx >> 2;
        int dq = bx & 3;
        float (*sq)[DD]  = (float(*)[DD]) sm;                 // 6272 floats
        float (*sw)[SP_] = (float(*)[SP_])(sm + 6272);        // 3136
        float* sinv = sm + 9408;                              // 49
        float* sden = sm + 9460;                              // 64
        for (int i = tid; i < NN * DD; i += 256) {
            size_t off = (size_t)bt * NN * DD + i;
            sq[i >> 7][i & 127] = g_qpart[0][off] + g_qpart[1][off]
                                + g_qpart[2][off] + g_qpart[3][off];
        }
        for (int i = tid; i < NN * SP_; i += 256)
            sw[i >> 6][i & 63] = g_ws[(size_t)bt * NN * SP_ + i];
        __syncthreads();
        int wid = tid >> 5, lane = tid & 31;
        for (int n = wid; n < NN; n += 8) {
            float v0 = sq[n][lane], v1 = sq[n][lane + 32],
                  v2 = sq[n][lane + 64], v3 = sq[n][lane + 96];
            float ss = v0 * v0 + v1 * v1 + v2 * v2 + v3 * v3;
            #pragma unroll
            for (int o = 16; o > 0; o >>= 1) ss += __shfl_xor_sync(0xffffffffu, ss, o);
            if (lane == 0) sinv[n] = 1.0f / fmaxf(sqrtf(ss), 1e-12f);
        }
        if (tid < SP_) {
            float s = 0.f;
            for (int n = 0; n < NN; n++) s += sw[n][tid];
            sden[tid] = 1.0f / (s + 1e-20f);
        }
        __syncthreads();
        for (int i = tid; i < NN * SP_; i += 256) {
            int n = i >> 6, s = i & 63;
            sw[n][s] *= sinv[n] * sden[s];
        }
        __syncthreads();
        int d  = tid & 31;
        int dd = dq * 32 + d;
        int sg = tid >> 5;
        float acc[8] = {};
        for (int n = 0; n < NN; n++) {
            float qv = sq[n][dd];
            #pragma unroll
            for (int i = 0; i < 8; i++)
                acc[i] = fmaf(sw[n][sg * 8 + i], qv, acc[i]);
        }
        #pragma unroll
        for (int i = 0; i < 8; i++)
            g_qsp[((size_t)bt * SP_ + sg * 8 + i) * DD + dd] = acc[i];
    }

    gridbar(0);

    // ======== phase 2: as1 (all 48 blocks) ========
    {
        int job = bx >> 3;
        int rb  = bx & 7;
        int r0  = rb * 8;
        int b = job / 3, t = job % 3;
        const float* X = g_qsp + (size_t)(b * T_ + t)     * SP_ * DD;
        const float* Y = g_qsp + (size_t)(b * T_ + t + 1) * SP_ * DD;
        float (*sYt)[65] = (float(*)[65])sm;                  // 8320 floats
        float (*sXr)[DD] = (float(*)[DD])(sm + 8320);         // 1024
        float (*sE)[65]  = (float(*)[65])(sm + 9344);         // 520
        for (int i = tid; i < SP_ * DD; i += 256) {
            int m = i >> 7, k = i & 127;
            sYt[k][m] = Y[i];
        }
        for (int i = tid; i < 8 * DD; i += 256) {
            int r = i >> 7, k = i & 127;
            sXr[r][k] = X[(size_t)(r0 + r) * DD + k];
        }
        __syncthreads();
        int m  = tid & 63;
        int lr = (tid >> 6) * 2;
        float a0 = 0.f, a1 = 0.f;
        #pragma unroll 8
        for (int k = 0; k < DD; k++) {
            float yv = sYt[k][m];
            a0 = fmaf(sXr[lr][k],     yv, a0);
            a1 = fmaf(sXr[lr + 1][k], yv, a1);
        }
        float e0 = expf(a0 * (1.0f / TEMP_)) - 1.0f;
        float e1 = expf(a1 * (1.0f / TEMP_)) - 1.0f;
        e0 *= e0; e1 *= e1;
        sE[lr][m] = e0; sE[lr + 1][m] = e1;
        g_E[(size_t)job * 4096 + (r0 + lr) * 64 + m]     = e0;
        g_E[(size_t)job * 4096 + (r0 + lr + 1) * 64 + m] = e1;
        __syncthreads();
        if (tid < 8) {
            float s = 0.f;
            for (int j = 0; j < 64; j++) s += sE[tid][j];
            g_rs[job * 64 + r0 + tid] = s;
        } else if (tid >= 64 && tid < 128) {
            int c = tid - 64;
            float s = 0.f;
            #pragma unroll
            for (int r = 0; r < 8; r++) s += sE[r][c];
            g_csp[(job * 8 + rb) * 64 + c] = s;
        }
    }

    gridbar(1);

    // ======== phase 3: chain (blocks 0..15) ========
    if (bx >= 16) return;
    {
        float* A12_1 = sm;
        float* A12_2 = sm + 1 * 64 * MSTRIDE;
        float* A21_2 = sm + 2 * 64 * MSTRIDE;
        float* A21_1 = sm + 3 * 64 * MSTRIDE;
        float* A21_0 = sm + 4 * 64 * MSTRIDE;
        float* buf0  = sm + 5 * 64 * MSTRIDE;
        float* buf1  = buf0 + 8 * BSTRIDE;
        float* bufP  = buf1 + 8 * BSTRIDE;
        float* sinvC = bufP + 8 * BSTRIDE;   // [384]
        float* slloss = sinvC + 384;         // [16]
        int b  = bx >> 3;
        int r0 = (bx & 7) * 8;
        int j0 = b * 3;

        // FIXED: strided loop covers all 384 entries with 256 threads
        for (int i = tid; i < 384; i += 256) {
            int kind = i >> 6, idx = i & 63;
            float v;
            if (kind < 3) {
                v = g_rs[(j0 + kind) * 64 + idx];
            } else {
                int j = j0 + (kind - 3);
                v = 0.f;
                #pragma unroll
                for (int rb = 0; rb < 8; rb++) v += g_csp[(j * 8 + rb) * 64 + idx];
            }
            sinvC[i] = 1.0f / (v + 1e-5f);
        }
        __syncthreads();

        const float* E0 = g_E + (size_t)j0 * 4096;
        const float* E1 = E0 + 4096;
        const float* E2 = E0 + 8192;
        for (int i = tid; i < 4096; i += 256) {
            int n = i >> 6, m = i & 63;
            float e1 = E1[i];
            A12_1[n * MSTRIDE + m] = e1 * sinvC[64 + n];
            A21_1[m * MSTRIDE + n] = e1 * sinvC[256 + m];
            float e2 = E2[i];
            A12_2[n * MSTRIDE + m] = e2 * sinvC[128 + n];
            A21_2[m * MSTRIDE + n] = e2 * sinvC[320 + m];
            float e0 = E0[i];
            A21_0[m * MSTRIDE + n] = e0 * sinvC[192 + m];
        }
        for (int i = tid; i < 512; i += 256) {
            int r = i >> 6, m = i & 63;
            buf0[r * BSTRIDE + m] = E0[(r0 + r) * 64 + m] * sinvC[r0 + r];
        }
        __syncthreads();

        mm8(buf0, A12_1, bufP);            // P = A12_0slice @ A12_1
        mm8(bufP, A21_1, buf0);
        mm8(buf0, A21_0, buf1);            // aa1 slice
        emit_aa(buf1, out, aa_base, 0, b, r0, slloss, write_loss);
        mm8(bufP, A12_2, buf0);
        mm8(buf0, A21_2, buf1);
        mm8(buf1, A21_1, buf0);
        mm8(buf0, A21_0, buf1);            // aa2 slice
        emit_aa(buf1, out, aa_base, 1, b, r0, slloss, write_loss);

        if (write_loss && tid == 0) {
            float s = 0.f;
            #pragma unroll
            for (int j = 0; j < 16; j++) s += slloss[j];
            atomicAdd(out, s * (1.0f / 128.0f));
        }
    }
}

// ---------------- launch ----------------
extern "C" void kernel_launch(void* const* d_in, const int* in_sizes, int n_in,
                              void* d_out, int out_size) {
    const float* feats   = (const float*)d_in[0];
    const float* W_head  = (const float*)d_in[1];
    const int*   sp_mask = (const int*)  d_in[2];
    float* out = (float*)d_out;

    int aa_base    = (out_size > 2 * B_ * SP_ * SP_) ? 1 : 0;
    int write_loss = aa_base;

    cudaFuncSetAttribute(mega_kernel, cudaFuncAttributeMaxDynamicSharedMemorySize, SMEM_MEGA);

    fused_in_kernel<<<588, 256>>>(sp_mask, feats, W_head, out, write_loss);
    mega_kernel    <<<NBLK, 256, SMEM_MEGA>>>(out, aa_base, write_loss);
}